// round 1
// baseline (speedup 1.0000x reference)
#include <cuda_runtime.h>
#include <math.h>

// ---------------- problem constants ----------------
#define C_      512
#define S_      8192          // T*H*W
#define HW_     1024          // H*W (frame size)
#define W_      32
#define NGROUP  32
#define CPG     16            // channels per group
#define KC      13824         // 512*27 (conv GEMM K)

// ---------------- scratch (device globals; no allocs allowed) ----------------
__device__ float g_mean[NGROUP];
__device__ float g_rstd[NGROUP];
__device__ float g_act[(size_t)C_ * S_];          // normalized(+silu) activation [c][s]
__device__ float g_col[(size_t)KC * S_];          // im2col, K-major [k][pos]  (452 MB)
__device__ float g_wT [(size_t)KC * C_];          // transposed conv weight [k][co]
__device__ float g_wsT[(size_t)C_ * C_];          // transposed 512x512 weight
__device__ float g_t1 [(size_t)C_ * S_];          // resnet mid / attention output
__device__ float g_y0 [(size_t)C_ * S_];          // resnet0 output (attn input)
__device__ float g_q  [(size_t)C_ * S_];          // Q [d][s]   (reused as resnet1 mid)
__device__ float g_kk [(size_t)C_ * S_];          // K [d][s]
__device__ float g_vv [(size_t)C_ * S_];          // V [d][s]
__device__ float g_p  [(size_t)S_ * S_];          // scores / probs [q][k]  (268 MB)
__device__ float g_o  [(size_t)S_ * C_];          // attn out [s][d]

// ---------------- reductions ----------------
__inline__ __device__ float warp_sum(float v) {
    #pragma unroll
    for (int o = 16; o; o >>= 1) v += __shfl_down_sync(0xffffffffu, v, o);
    return v;
}
__inline__ __device__ float warp_max(float v) {
    #pragma unroll
    for (int o = 16; o; o >>= 1) v = fmaxf(v, __shfl_down_sync(0xffffffffu, v, o));
    return v;
}

// ---------------- GroupNorm statistics: one block per group ----------------
__global__ void gn_stats_k(const float* __restrict__ x) {
    int g = blockIdx.x;
    const float4* p = (const float4*)(x + (size_t)g * CPG * S_);
    const int n4 = (CPG * S_) / 4;
    float s = 0.f, s2 = 0.f;
    for (int i = threadIdx.x; i < n4; i += blockDim.x) {
        float4 v = p[i];
        s  += v.x + v.y + v.z + v.w;
        s2 += v.x * v.x + v.y * v.y + v.z * v.z + v.w * v.w;
    }
    __shared__ float sh0[8], sh1[8];
    float ws = warp_sum(s), ws2 = warp_sum(s2);
    int wid = threadIdx.x >> 5, lid = threadIdx.x & 31;
    if (!lid) { sh0[wid] = ws; sh1[wid] = ws2; }
    __syncthreads();
    if (threadIdx.x == 0) {
        float a = 0.f, b = 0.f;
        #pragma unroll
        for (int i = 0; i < 8; i++) { a += sh0[i]; b += sh1[i]; }
        const float inv_n = 1.f / (float)(CPG * S_);
        float m   = a * inv_n;
        float var = b * inv_n - m * m;
        g_mean[g] = m;
        g_rstd[g] = rsqrtf(var + 1e-6f);
    }
}

// ---------------- normalize (+optional SiLU) ----------------
__global__ void normact_k(const float* __restrict__ x, const float* __restrict__ sc,
                          const float* __restrict__ bi, float* __restrict__ out, int do_silu) {
    int i = blockIdx.x * blockDim.x + threadIdx.x;   // over C_*S_
    int c = i >> 13;                                 // / 8192
    int g = c >> 4;
    float v = (x[i] - g_mean[g]) * g_rstd[g] * sc[c] + bi[c];
    if (do_silu) v = v / (1.f + __expf(-v));
    out[i] = v;
}

// ---------------- im2col (causal/replicate padding), K-major output ----------------
__global__ void im2col_k() {
    int k   = blockIdx.y;                       // 0..13823
    int pos = blockIdx.x * blockDim.x + threadIdx.x;  // 0..8191
    int ci = k / 27;
    int r  = k - ci * 27;
    int kd = r / 9;  r -= kd * 9;
    int kh = r / 3;
    int kw = r - kh * 3;
    int t   = pos >> 10;
    int rem = pos & 1023;
    int y   = rem >> 5;
    int x   = rem & 31;
    int ts = min(max(t + kd - 2, 0), 7);
    int ys = min(max(y + kh - 1, 0), 31);
    int xs = min(max(x + kw - 1, 0), 31);
    g_col[(size_t)k * S_ + pos] = g_act[(size_t)ci * S_ + ts * HW_ + ys * W_ + xs];
}

// ---------------- tiled transpose: in [R][Cc] -> out [Cc][R] (dims % 32 == 0) --------
__global__ void transpose_k(const float* __restrict__ in, float* __restrict__ out,
                            int R, int Cc) {
    __shared__ float tile[32][33];
    int c0 = blockIdx.x * 32, r0 = blockIdx.y * 32;
    int tx = threadIdx.x, ty = threadIdx.y;
    #pragma unroll
    for (int i = ty; i < 32; i += 8)
        tile[i][tx] = in[(size_t)(r0 + i) * Cc + c0 + tx];
    __syncthreads();
    #pragma unroll
    for (int i = ty; i < 32; i += 8)
        out[(size_t)(c0 + i) * R + r0 + tx] = tile[tx][i];
}

// ---------------- SGEMM "TT":  C[m][n] = sum_k A[k][m] * B[k][n] ----------------
// 128x128 block tile, BK=8, 256 threads, 8x8 per thread.
// causal==1: skip tiles with n0 >= ((m0/1024)+1)*1024 (block-causal frame mask).
__global__ void __launch_bounds__(256) gemm_tt_k(
    const float* __restrict__ A, const float* __restrict__ B, float* __restrict__ C,
    int M, int N, int K, int lda, int ldb, int ldc,
    float alpha, const float* __restrict__ bias, const float* __restrict__ addend,
    int causal) {
    int n0 = blockIdx.x * 128, m0 = blockIdx.y * 128;
    if (causal && n0 >= (((m0 >> 10) + 1) << 10)) return;

    __shared__ float As[8][128];
    __shared__ float Bs[8][128];
    int tid = threadIdx.x;
    int lk = tid >> 5, lm = (tid & 31) << 2;
    const float* Ag = A + (size_t)lk * lda + m0 + lm;
    const float* Bg = B + (size_t)lk * ldb + n0 + lm;
    int tx = tid & 15, ty = tid >> 4;

    float acc[8][8];
    #pragma unroll
    for (int i = 0; i < 8; i++)
        #pragma unroll
        for (int j = 0; j < 8; j++) acc[i][j] = 0.f;

    for (int k0 = 0; k0 < K; k0 += 8) {
        float4 av = *(const float4*)Ag;
        float4 bv = *(const float4*)Bg;
        *(float4*)&As[lk][lm] = av;
        *(float4*)&Bs[lk][lm] = bv;
        __syncthreads();
        #pragma unroll
        for (int kkk = 0; kkk < 8; kkk++) {
            float a[8], b[8];
            *(float4*)&a[0] = *(const float4*)&As[kkk][ty << 2];
            *(float4*)&a[4] = *(const float4*)&As[kkk][(ty << 2) + 64];
            *(float4*)&b[0] = *(const float4*)&Bs[kkk][tx << 2];
            *(float4*)&b[4] = *(const float4*)&Bs[kkk][(tx << 2) + 64];
            #pragma unroll
            for (int ii = 0; ii < 8; ii++)
                #pragma unroll
                for (int jj = 0; jj < 8; jj++) acc[ii][jj] += a[ii] * b[jj];
        }
        __syncthreads();
        Ag += lda << 3;
        Bg += ldb << 3;
    }

    #pragma unroll
    for (int ii = 0; ii < 8; ii++) {
        int m = m0 + ((ii < 4) ? (ty << 2) + ii : 60 + (ty << 2) + ii);
        float bval = bias ? bias[m] : 0.f;
        #pragma unroll
        for (int jj = 0; jj < 8; jj++) {
            int n = n0 + ((jj < 4) ? (tx << 2) + jj : 60 + (tx << 2) + jj);
            float v = acc[ii][jj] * alpha + bval;
            if (addend) v += addend[(size_t)m * ldc + n];
            C[(size_t)m * ldc + n] = v;
        }
    }
}

// ---------------- SGEMM "NT":  C[m][n] = sum_k A[m][k] * B[n][k] ----------------
// kcausal==1: per-block K bound = ((m0/1024)+1)*1024 (variable key length in P*V).
__global__ void __launch_bounds__(256) gemm_nt_k(
    const float* __restrict__ A, const float* __restrict__ B, float* __restrict__ C,
    int M, int N, int K, int lda, int ldb, int ldc,
    float alpha, const float* __restrict__ bias, const float* __restrict__ addend,
    int kcausal) {
    int n0 = blockIdx.x * 128, m0 = blockIdx.y * 128;
    int Keff = kcausal ? (((m0 >> 10) + 1) << 10) : K;

    __shared__ float As[8][132];
    __shared__ float Bs[8][132];
    int tid = threadIdx.x;
    int lr = tid >> 1, lq = (tid & 1) << 2;
    const float* Ag = A + (size_t)(m0 + lr) * lda + lq;
    const float* Bg = B + (size_t)(n0 + lr) * ldb + lq;
    int tx = tid & 15, ty = tid >> 4;

    float acc[8][8];
    #pragma unroll
    for (int i = 0; i < 8; i++)
        #pragma unroll
        for (int j = 0; j < 8; j++) acc[i][j] = 0.f;

    for (int k0 = 0; k0 < Keff; k0 += 8) {
        float4 av = *(const float4*)(Ag + k0);
        float4 bv = *(const float4*)(Bg + k0);
        As[lq + 0][lr] = av.x; As[lq + 1][lr] = av.y;
        As[lq + 2][lr] = av.z; As[lq + 3][lr] = av.w;
        Bs[lq + 0][lr] = bv.x; Bs[lq + 1][lr] = bv.y;
        Bs[lq + 2][lr] = bv.z; Bs[lq + 3][lr] = bv.w;
        __syncthreads();
        #pragma unroll
        for (int kkk = 0; kkk < 8; kkk++) {
            float a[8], b[8];
            *(float4*)&a[0] = *(const float4*)&As[kkk][ty << 2];
            *(float4*)&a[4] = *(const float4*)&As[kkk][(ty << 2) + 64];
            *(float4*)&b[0] = *(const float4*)&Bs[kkk][tx << 2];
            *(float4*)&b[4] = *(const float4*)&Bs[kkk][(tx << 2) + 64];
            #pragma unroll
            for (int ii = 0; ii < 8; ii++)
                #pragma unroll
                for (int jj = 0; jj < 8; jj++) acc[ii][jj] += a[ii] * b[jj];
        }
        __syncthreads();
    }

    #pragma unroll
    for (int ii = 0; ii < 8; ii++) {
        int m = m0 + ((ii < 4) ? (ty << 2) + ii : 60 + (ty << 2) + ii);
        float bval = bias ? bias[m] : 0.f;
        #pragma unroll
        for (int jj = 0; jj < 8; jj++) {
            int n = n0 + ((jj < 4) ? (tx << 2) + jj : 60 + (tx << 2) + jj);
            float v = acc[ii][jj] * alpha + bval;
            if (addend) v += addend[(size_t)m * ldc + n];
            C[(size_t)m * ldc + n] = v;
        }
    }
}

// ---------------- row softmax over causal length L(i) ----------------
__global__ void softmax_k() {
    int i = blockIdx.x;                         // query row
    int L = ((i >> 10) + 1) << 10;              // allowed key count
    float4* row = (float4*)(g_p + (size_t)i * (size_t)S_);
    int n4 = L >> 2;
    int tid = threadIdx.x;
    __shared__ float sh[8];

    float mx = -1e30f;
    for (int j = tid; j < n4; j += 256) {
        float4 v = row[j];
        mx = fmaxf(mx, fmaxf(fmaxf(v.x, v.y), fmaxf(v.z, v.w)));
    }
    float wm = warp_max(mx);
    if ((tid & 31) == 0) sh[tid >> 5] = wm;
    __syncthreads();
    if (tid < 32) {
        float m2 = (tid < 8) ? sh[tid] : -1e30f;
        m2 = warp_max(m2);
        if (tid == 0) sh[0] = m2;
    }
    __syncthreads();
    float m = sh[0];
    __syncthreads();

    float s = 0.f;
    for (int j = tid; j < n4; j += 256) {
        float4 v = row[j];
        v.x = __expf(v.x - m); v.y = __expf(v.y - m);
        v.z = __expf(v.z - m); v.w = __expf(v.w - m);
        s += v.x + v.y + v.z + v.w;
        row[j] = v;
    }
    float ws = warp_sum(s);
    if ((tid & 31) == 0) sh[tid >> 5] = ws;
    __syncthreads();
    if (tid < 32) {
        float s2 = (tid < 8) ? sh[tid] : 0.f;
        s2 = warp_sum(s2);
        if (tid == 0) sh[0] = s2;
    }
    __syncthreads();
    float inv = 1.f / sh[0];
    for (int j = tid; j < n4; j += 256) {
        float4 v = row[j];
        v.x *= inv; v.y *= inv; v.z *= inv; v.w *= inv;
        row[j] = v;
    }
}

// ---------------- orchestration ----------------
extern "C" void kernel_launch(void* const* d_in, const int* in_sizes, int n_in,
                              void* d_out, int out_size) {
    (void)in_sizes; (void)n_in; (void)out_size;

    float *act, *col, *wT, *wsT, *t1, *y0, *q, *kb, *vb, *p, *o;
    cudaGetSymbolAddress((void**)&act, g_act);
    cudaGetSymbolAddress((void**)&col, g_col);
    cudaGetSymbolAddress((void**)&wT,  g_wT);
    cudaGetSymbolAddress((void**)&wsT, g_wsT);
    cudaGetSymbolAddress((void**)&t1,  g_t1);
    cudaGetSymbolAddress((void**)&y0,  g_y0);
    cudaGetSymbolAddress((void**)&q,   g_q);
    cudaGetSymbolAddress((void**)&kb,  g_kk);
    cudaGetSymbolAddress((void**)&vb,  g_vv);
    cudaGetSymbolAddress((void**)&p,   g_p);
    cudaGetSymbolAddress((void**)&o,   g_o);

    const float* X = (const float*)d_in[0];
    // resnet0: 1..8, resnet1: 9..16, attention: 17..26
    const float* a_gns = (const float*)d_in[17];
    const float* a_gnb = (const float*)d_in[18];
    const float* a_wq  = (const float*)d_in[19];
    const float* a_bq  = (const float*)d_in[20];
    const float* a_wk  = (const float*)d_in[21];
    const float* a_bk  = (const float*)d_in[22];
    const float* a_wv  = (const float*)d_in[23];
    const float* a_bv  = (const float*)d_in[24];
    const float* a_wo  = (const float*)d_in[25];
    const float* a_bo  = (const float*)d_in[26];

    const dim3 tr_t(32, 8);
    const dim3 gemm_conv(S_ / 128, C_ / 128);   // (64, 4)

    auto resnet = [&](const float* in, int base, float* mid, float* outbuf) {
        const float* n1s = (const float*)d_in[base + 0];
        const float* n1b = (const float*)d_in[base + 1];
        const float* w1  = (const float*)d_in[base + 2];
        const float* b1  = (const float*)d_in[base + 3];
        const float* n2s = (const float*)d_in[base + 4];
        const float* n2b = (const float*)d_in[base + 5];
        const float* w2  = (const float*)d_in[base + 6];
        const float* b2  = (const float*)d_in[base + 7];

        gn_stats_k<<<NGROUP, 256>>>(in);
        normact_k<<<(C_ * S_) / 256, 256>>>(in, n1s, n1b, act, 1);
        im2col_k<<<dim3(S_ / 256, KC), 256>>>();
        transpose_k<<<dim3(KC / 32, C_ / 32), tr_t>>>(w1, wT, C_, KC);
        gemm_tt_k<<<gemm_conv, 256>>>(wT, col, mid, C_, S_, KC, C_, S_, S_,
                                      1.f, b1, nullptr, 0);
        gn_stats_k<<<NGROUP, 256>>>(mid);
        normact_k<<<(C_ * S_) / 256, 256>>>(mid, n2s, n2b, act, 1);
        im2col_k<<<dim3(S_ / 256, KC), 256>>>();
        transpose_k<<<dim3(KC / 32, C_ / 32), tr_t>>>(w2, wT, C_, KC);
        gemm_tt_k<<<gemm_conv, 256>>>(wT, col, outbuf, C_, S_, KC, C_, S_, S_,
                                      1.f, b2, in, 0);
    };

    // ---- ResNet block 0:  X -> y0 ----
    resnet(X, 1, t1, y0);

    // ---- Causal frame attention on y0 ([c][s] == b,c,(f h w)) ----
    gn_stats_k<<<NGROUP, 256>>>(y0);
    normact_k<<<(C_ * S_) / 256, 256>>>(y0, a_gns, a_gnb, act, 0);

    transpose_k<<<dim3(16, 16), tr_t>>>(a_wq, wsT, C_, C_);
    gemm_tt_k<<<dim3(64, 4), 256>>>(wsT, act, q,  C_, S_, C_, C_, S_, S_, 1.f, a_bq, nullptr, 0);
    transpose_k<<<dim3(16, 16), tr_t>>>(a_wk, wsT, C_, C_);
    gemm_tt_k<<<dim3(64, 4), 256>>>(wsT, act, kb, C_, S_, C_, C_, S_, S_, 1.f, a_bk, nullptr, 0);
    transpose_k<<<dim3(16, 16), tr_t>>>(a_wv, wsT, C_, C_);
    gemm_tt_k<<<dim3(64, 4), 256>>>(wsT, act, vb, C_, S_, C_, C_, S_, S_, 1.f, a_bv, nullptr, 0);

    // scores[i][j] = (Q . K) / sqrt(512), block-causal tile skip
    gemm_tt_k<<<dim3(64, 64), 256>>>(q, kb, p, S_, S_, C_, S_, S_, S_,
                                     0.04419417382415922f, nullptr, nullptr, 1);
    softmax_k<<<S_, 256>>>();
    // O[s][d] = P . V   (variable K per query frame)
    gemm_nt_k<<<dim3(4, 64), 256>>>(p, vb, o, S_, C_, S_, S_, S_, C_,
                                    1.f, nullptr, nullptr, 1);
    // out[c][s] = Wo . O + bo + y0  (residual)
    gemm_nt_k<<<dim3(64, 4), 256>>>(a_wo, o, t1, C_, S_, C_, C_, C_, S_,
                                    1.f, a_bo, y0, 0);

    // ---- ResNet block 1:  t1 -> d_out ----
    resnet(t1, 9, q, (float*)d_out);
}